// round 13
// baseline (speedup 1.0000x reference)
#include <cuda_runtime.h>
#include <cuda_fp16.h>
#include <math_constants.h>

// GATv2 additive attention + masked softmax, v9 (occupancy 3).
// - fp16 q,k,a in smem (q,k pre-scaled 0.5); silu + a-product in fp16
//   (HADD2 + tanh.approx.f16x2 + 2x HFMA2), flushed to fp32 every 8 d-values.
// - class-interleaved compaction -> gather LDS.128 at the 4-phase floor.
// - __launch_bounds__(256,3): 3 CTAs/SM (188KB smem), 24 warps/SM; register
//   pressure cut by re-reading compacted indices from smem per pair.
// score(b,h,i,j) = sum_d a[h,d]*silu(q+k); silu(s)=u*(1+tanh(u)), u=s/2.

#define B_   2
#define H_   8
#define LQ_  384
#define LK_  384
#define D_   64
#define ROWS 8            // q rows per block, 1 warp per row
#define NC   12           // LK/32 chunks
#define KSTR 144          // K smem row stride in BYTES (row data = 128B fp16)
#define INVALID16 0xFFFFu

__device__ __forceinline__ __half2 tanh2_approx(__half2 x) {
    unsigned r, xi = *reinterpret_cast<unsigned*>(&x);
    asm("tanh.approx.f16x2 %0, %1;" : "=r"(r) : "r"(xi));
    return *reinterpret_cast<__half2*>(&r);
}
#define H2(u) (*reinterpret_cast<const __half2*>(&(u)))

__global__ __launch_bounds__(256, 3)
void gatv2_kernel(const float* __restrict__ q, const float* __restrict__ k,
                  const float* __restrict__ att, const int* __restrict__ mask,
                  float* __restrict__ out)
{
    extern __shared__ float smem[];
    // layout: K fp16 [LK][KSTR B] | q fp16 [ROWS][128B] | a fp16 [128B] | idx16 [ROWS][LK]
    char*  ksb = (char*)smem;
    char*  qsb = ksb + LK_ * KSTR;                       // 8 * 128B
    char*  asb = qsb + ROWS * 128;                       // 64 halfs = 128B
    unsigned short* idxb = (unsigned short*)(asb + 128); // [ROWS][LK]

    const int ntiles = LQ_ / ROWS;       // 48
    int blk   = blockIdx.x;
    int bh    = blk / ntiles;
    int itile = blk - bh * ntiles;
    int h     = bh & (H_ - 1);
    int tid   = threadIdx.x;
    int warp  = tid >> 5, lane = tid & 31;
    int i     = itile * ROWS + warp;

    // ---- stage 0.5*K as fp16 (144B stride) ----
    const float4* kg = (const float4*)(k + (size_t)bh * LK_ * D_);
    for (int idxr = tid; idxr < LK_ * D_ / 4; idxr += 256) {
        int j = idxr >> 4, d4 = idxr & 15;
        float4 v = kg[idxr];
        uint2 w;
        *reinterpret_cast<__half2*>(&w.x) = __floats2half2_rn(0.5f * v.x, 0.5f * v.y);
        *reinterpret_cast<__half2*>(&w.y) = __floats2half2_rn(0.5f * v.z, 0.5f * v.w);
        *reinterpret_cast<uint2*>(ksb + j * KSTR + d4 * 8) = w;
    }
    // ---- stage 0.5*q as fp16 (128B rows) ----
    const float4* qg = (const float4*)(q + ((size_t)bh * LQ_ + itile * ROWS) * D_);
    for (int idxr = tid; idxr < ROWS * D_ / 4; idxr += 256) {
        int r = idxr >> 4, d4 = idxr & 15;
        float4 v = qg[idxr];
        uint2 w;
        *reinterpret_cast<__half2*>(&w.x) = __floats2half2_rn(0.5f * v.x, 0.5f * v.y);
        *reinterpret_cast<__half2*>(&w.y) = __floats2half2_rn(0.5f * v.z, 0.5f * v.w);
        *reinterpret_cast<uint2*>(qsb + r * 128 + d4 * 8) = w;
    }
    // ---- stage a as fp16 ----
    if (tid < 32) {
        __half2 a2 = __floats2half2_rn(att[h * D_ + 2 * tid], att[h * D_ + 2 * tid + 1]);
        reinterpret_cast<__half2*>(asb)[tid] = a2;
    }

    // ---- class-interleaved compaction (warp-private stripe) ----
    unsigned short* stripe = idxb + warp * LK_;
    {
        unsigned* sw = (unsigned*)stripe;
#pragma unroll
        for (int r = 0; r < 6; r++) sw[lane + 32 * r] = 0xFFFFFFFFu;
    }
    __syncwarp();

    const int* mrow = mask + ((size_t)bh * LQ_ + i) * LK_;
    unsigned km = 0;                       // per-lane 12-bit keep mask
#pragma unroll
    for (int c = 0; c < NC; c++)
        if (mrow[c * 32 + lane] == 0) km |= (1u << c);
    int cnt = __popc(km);

    // prefix among the 4 lanes of my bank-class (lane&7)
    int c8  = __shfl_up_sync(0xffffffffu, cnt, 8);
    int c16 = __shfl_up_sync(0xffffffffu, cnt, 16);
    int c24 = __shfl_up_sync(0xffffffffu, cnt, 24);
    int p = (lane >= 8 ? c8 : 0) + (lane >= 16 ? c16 : 0) + (lane >= 24 ? c24 : 0);

    {
        int r = 0;
        unsigned m = km;
#pragma unroll
        for (int c = 0; c < NC; c++) {
            if (m & 1u) { stripe[(lane & 7) + 8 * (p + r)] = (unsigned short)(c * 32 + lane); r++; }
            m >>= 1;
        }
    }
    int tot = p + cnt;                                    // lane 24+c holds class-c total
    int nmax = __shfl_sync(0xffffffffu, tot, 24 + (lane & 7));
#pragma unroll
    for (int o = 1; o <= 4; o <<= 1) nmax = max(nmax, __shfl_xor_sync(0xffffffffu, nmax, o));
    int nchunk = (nmax + 3) >> 2;                         // ceil(8*Nmax/32)

    __syncthreads();                                      // staging + stripes visible

    const uint4* qrow4 = (const uint4*)(qsb + warp * 128);
    const uint4* arow4 = (const uint4*)asb;
    float acc[NC];
#pragma unroll
    for (int cc = 0; cc < NC; cc++) acc[cc] = -CUDART_INF_F;

    __half2 hz = __floats2half2_rn(0.f, 0.f);

#define STEP(HACC, QW, KW, AW)                                         \
    {                                                                  \
        __half2 u2 = __hadd2(H2(QW), H2(KW));                          \
        __half2 t2 = tanh2_approx(u2);                                 \
        __half2 sl = __hfma2(u2, t2, u2);                              \
        HACC = __hfma2(H2(AW), sl, HACC);                              \
    }

    // ---- chunk-pair score loop (indices re-read from smem: low reg pressure) ----
#pragma unroll
    for (int pp = 0; pp < NC / 2; pp++) {
        if (2 * pp < nchunk) {
            unsigned short v0 = stripe[(2 * pp)     * 32 + lane];
            unsigned short v1 = stripe[(2 * pp + 1) * 32 + lane];
            int val0 = (v0 != (unsigned short)INVALID16);
            int val1 = (v1 != (unsigned short)INVALID16);
            const uint4* kr0 = (const uint4*)(ksb + (val0 ? (int)v0 : 0) * KSTR);
            const uint4* kr1 = (const uint4*)(ksb + (val1 ? (int)v1 : 0) * KSTR);
            float sA0 = 0.f, sA1 = 0.f, sB0 = 0.f, sB1 = 0.f;
#pragma unroll 4
            for (int cI = 0; cI < 8; cI++) {             // 8 d-values per iter
                uint4 qa = qrow4[cI];
                uint4 aw = arow4[cI];
                uint4 ka = kr0[cI];
                uint4 kb = kr1[cI];
                __half2 hA01 = hz, hA23 = hz, hB01 = hz, hB23 = hz;
                STEP(hA01, qa.x, ka.x, aw.x); STEP(hA01, qa.y, ka.y, aw.y);
                STEP(hA23, qa.z, ka.z, aw.z); STEP(hA23, qa.w, ka.w, aw.w);
                STEP(hB01, qa.x, kb.x, aw.x); STEP(hB01, qa.y, kb.y, aw.y);
                STEP(hB23, qa.z, kb.z, aw.z); STEP(hB23, qa.w, kb.w, aw.w);
                float2 f;
                f = __half22float2(hA01); sA0 += f.x; sA0 += f.y;
                f = __half22float2(hA23); sA1 += f.x; sA1 += f.y;
                f = __half22float2(hB01); sB0 += f.x; sB0 += f.y;
                f = __half22float2(hB23); sB1 += f.x; sB1 += f.y;
            }
            acc[2 * pp]     = val0 ? (sA0 + sA1) : -CUDART_INF_F;
            acc[2 * pp + 1] = val1 ? (sB0 + sB1) : -CUDART_INF_F;
        }
    }
#undef STEP

    // ---- softmax over compacted values ----
    float mx = -CUDART_INF_F;
#pragma unroll
    for (int cc = 0; cc < NC; cc++) mx = fmaxf(mx, acc[cc]);
#pragma unroll
    for (int o = 16; o; o >>= 1) mx = fmaxf(mx, __shfl_xor_sync(0xffffffffu, mx, o));

    float sum = 0.f;
#pragma unroll
    for (int cc = 0; cc < NC; cc++) {
        float e = __expf(acc[cc] - mx);
        acc[cc] = e;
        sum += e;
    }
#pragma unroll
    for (int o = 16; o; o >>= 1) sum += __shfl_xor_sync(0xffffffffu, sum, o);
    float inv = (sum > 0.f) ? __fdividef(1.f, sum) : 0.f;

    // ---- scatter via smem (reuse K region after barrier), dense store ----
    __syncthreads();
    float* ws = (float*)ksb + warp * LK_;
#pragma unroll
    for (int c = 0; c < NC; c++) ws[c * 32 + lane] = 0.f;
    __syncwarp();
#pragma unroll
    for (int cc = 0; cc < NC; cc++) {
        unsigned short v = stripe[cc * 32 + lane];
        if (v != (unsigned short)INVALID16) ws[v] = acc[cc] * inv;
    }
    __syncwarp();

    float* orow = out + ((size_t)bh * LQ_ + i) * LK_;
#pragma unroll
    for (int c = 0; c < NC; c++) orow[c * 32 + lane] = ws[c * 32 + lane];
}

extern "C" void kernel_launch(void* const* d_in, const int* in_sizes, int n_in,
                              void* d_out, int out_size)
{
    const float* q   = (const float*)d_in[0];
    const float* k   = (const float*)d_in[1];
    const float* att = (const float*)d_in[2];
    const int*   m   = (const int*)d_in[3];
    float* out       = (float*)d_out;

    // K 55296 + q 1024 + a 128 + idx16 6144 = 62,592 B
    const int smem_bytes = LK_ * KSTR + ROWS * 128 + 128
                         + ROWS * LK_ * (int)sizeof(unsigned short);
    cudaFuncSetAttribute(gatv2_kernel, cudaFuncAttributeMaxDynamicSharedMemorySize, smem_bytes);

    dim3 grid(B_ * H_ * (LQ_ / ROWS));   // 768
    gatv2_kernel<<<grid, 256, smem_bytes>>>(q, k, att, m, out);
}

// round 14
// speedup vs baseline: 1.0384x; 1.0384x over previous
#include <cuda_runtime.h>
#include <cuda_fp16.h>
#include <math_constants.h>

// GATv2 additive attention + masked softmax, v10 (hybrid compaction).
// - fp16 q,k,a in smem (q,k pre-scaled 0.5); silu + a-product in fp16
//   (HADD2 + tanh.approx.f16x2 + 2x HFMA2), flushed to fp32 every 8 d-values.
// - HYBRID compaction: slots [0,32*Cfull) perfectly bank-class-balanced
//   (4/class per 32-slot chunk -> 4-phase gather floor), class overflow packed
//   densely after (contiguous validity, nchunk = ceil(nkeep/32), no padding).
// score(b,h,i,j) = sum_d a[h,d]*silu(q+k); silu(s)=u*(1+tanh(u)), u=s/2.

#define B_   2
#define H_   8
#define LQ_  384
#define LK_  384
#define D_   64
#define ROWS 8            // q rows per block, 1 warp per row
#define NC   12           // LK/32 chunks
#define KSTR 144          // K smem row stride in BYTES (row data = 128B fp16)
#define FULLM 0xffffffffu

__device__ __forceinline__ __half2 tanh2_approx(__half2 x) {
    unsigned r, xi = *reinterpret_cast<unsigned*>(&x);
    asm("tanh.approx.f16x2 %0, %1;" : "=r"(r) : "r"(xi));
    return *reinterpret_cast<__half2*>(&r);
}
#define H2(u) (*reinterpret_cast<const __half2*>(&(u)))

__global__ __launch_bounds__(256, 3)
void gatv2_kernel(const float* __restrict__ q, const float* __restrict__ k,
                  const float* __restrict__ att, const int* __restrict__ mask,
                  float* __restrict__ out)
{
    extern __shared__ float smem[];
    // layout: K fp16 [LK][KSTR B] | q fp16 [ROWS][128B] | a fp16 [128B] | idx16 [ROWS][LK]
    char*  ksb = (char*)smem;
    char*  qsb = ksb + LK_ * KSTR;                       // 8 * 128B
    char*  asb = qsb + ROWS * 128;                       // 64 halfs = 128B
    unsigned short* idxb = (unsigned short*)(asb + 128); // [ROWS][LK]

    const int ntiles = LQ_ / ROWS;       // 48
    int blk   = blockIdx.x;
    int bh    = blk / ntiles;
    int itile = blk - bh * ntiles;
    int h     = bh & (H_ - 1);
    int tid   = threadIdx.x;
    int warp  = tid >> 5, lane = tid & 31;
    int i     = itile * ROWS + warp;

    // ---- stage 0.5*K as fp16 (144B stride) ----
    const float4* kg = (const float4*)(k + (size_t)bh * LK_ * D_);
    for (int idxr = tid; idxr < LK_ * D_ / 4; idxr += 256) {
        int j = idxr >> 4, d4 = idxr & 15;
        float4 v = kg[idxr];
        uint2 w;
        *reinterpret_cast<__half2*>(&w.x) = __floats2half2_rn(0.5f * v.x, 0.5f * v.y);
        *reinterpret_cast<__half2*>(&w.y) = __floats2half2_rn(0.5f * v.z, 0.5f * v.w);
        *reinterpret_cast<uint2*>(ksb + j * KSTR + d4 * 8) = w;
    }
    // ---- stage 0.5*q as fp16 (128B rows) ----
    const float4* qg = (const float4*)(q + ((size_t)bh * LQ_ + itile * ROWS) * D_);
    for (int idxr = tid; idxr < ROWS * D_ / 4; idxr += 256) {
        int r = idxr >> 4, d4 = idxr & 15;
        float4 v = qg[idxr];
        uint2 w;
        *reinterpret_cast<__half2*>(&w.x) = __floats2half2_rn(0.5f * v.x, 0.5f * v.y);
        *reinterpret_cast<__half2*>(&w.y) = __floats2half2_rn(0.5f * v.z, 0.5f * v.w);
        *reinterpret_cast<uint2*>(qsb + r * 128 + d4 * 8) = w;
    }
    // ---- stage a as fp16 ----
    if (tid < 32) {
        __half2 a2 = __floats2half2_rn(att[h * D_ + 2 * tid], att[h * D_ + 2 * tid + 1]);
        reinterpret_cast<__half2*>(asb)[tid] = a2;
    }

    // ---- hybrid compaction (warp-private stripe) ----
    const int* mrow = mask + ((size_t)bh * LQ_ + i) * LK_;
    unsigned short* stripe = idxb + warp * LK_;
    unsigned km = 0;                       // per-lane 12-bit keep mask
#pragma unroll
    for (int c = 0; c < NC; c++)
        if (mrow[c * 32 + lane] == 0) km |= (1u << c);
    int cnt = __popc(km);

    // class-rank prefix (lanes of my bank-class (lane&7) below me)
    int c8  = __shfl_up_sync(FULLM, cnt, 8);
    int c16 = __shfl_up_sync(FULLM, cnt, 16);
    int c24 = __shfl_up_sync(FULLM, cnt, 24);
    int p = (lane >= 8 ? c8 : 0) + (lane >= 16 ? c16 : 0) + (lane >= 24 ? c24 : 0);
    int tot = p + cnt;                     // at lane 24+c: total count of class c

    int myclass = lane & 7;
    // class totals: min/max over classes (value constant within a class)
    int Nme = __shfl_sync(FULLM, tot, 24 + myclass);
    int nmin = Nme;
#pragma unroll
    for (int o = 1; o <= 4; o <<= 1) nmin = min(nmin, __shfl_xor_sync(FULLM, nmin, o));
    int Cfull = nmin >> 2;
    int bal   = 4 * Cfull;                 // balanced entries per class

    // exclusive scan of class overflow (N_k - bal) over classes below mine
    int myscan = 0;
#pragma unroll
    for (int kk = 0; kk < 7; kk++) {
        int Nk = __shfl_sync(FULLM, tot, 24 + kk);
        if (kk < myclass) myscan += (Nk - bal);
    }
    // nkeep = warp total
    int nkeep = cnt;
#pragma unroll
    for (int o = 1; o <= 16; o <<= 1) nkeep += __shfl_xor_sync(FULLM, nkeep, o);
    int nchunk = (nkeep + 31) >> 5;

    // scatter kept j's: balanced body then dense overflow tail
    {
        int r = 0;
        unsigned m = km;
#pragma unroll
        for (int c = 0; c < NC; c++) {
            if (m & 1u) {
                int g = p + r;             // my rank within my class's list
                int slot = (g < bal) ? (myclass + 8 * g)
                                     : (8 * bal + myscan + (g - bal));
                stripe[slot] = (unsigned short)(c * 32 + lane);
                r++;
            }
            m >>= 1;
        }
    }

    __syncthreads();                       // staging + stripes visible

    const uint4* qrow4 = (const uint4*)(qsb + warp * 128);
    const uint4* arow4 = (const uint4*)asb;
    float acc[NC];
#pragma unroll
    for (int cc = 0; cc < NC; cc++) acc[cc] = -CUDART_INF_F;

    __half2 hz = __floats2half2_rn(0.f, 0.f);

#define STEP(HACC, QW, KW, AW)                                         \
    {                                                                  \
        __half2 u2 = __hadd2(H2(QW), H2(KW));                          \
        __half2 t2 = tanh2_approx(u2);                                 \
        __half2 sl = __hfma2(u2, t2, u2);                              \
        HACC = __hfma2(H2(AW), sl, HACC);                              \
    }

    // ---- chunk-pair score loop (contiguous validity: slot < nkeep) ----
#pragma unroll
    for (int pp = 0; pp < NC / 2; pp++) {
        if (2 * pp < nchunk) {
            int s0i = (2 * pp)     * 32 + lane;
            int s1i = (2 * pp + 1) * 32 + lane;
            int val0 = s0i < nkeep;
            int val1 = s1i < nkeep;
            int j0 = val0 ? (int)stripe[s0i] : 0;
            int j1 = val1 ? (int)stripe[s1i] : 0;
            const uint4* kr0 = (const uint4*)(ksb + j0 * KSTR);
            const uint4* kr1 = (const uint4*)(ksb + j1 * KSTR);
            float sA0 = 0.f, sA1 = 0.f, sB0 = 0.f, sB1 = 0.f;
#pragma unroll 4
            for (int cI = 0; cI < 8; cI++) {             // 8 d-values per iter
                uint4 qa = qrow4[cI];
                uint4 aw = arow4[cI];
                uint4 ka = kr0[cI];
                uint4 kb = kr1[cI];
                __half2 hA01 = hz, hA23 = hz, hB01 = hz, hB23 = hz;
                STEP(hA01, qa.x, ka.x, aw.x); STEP(hA01, qa.y, ka.y, aw.y);
                STEP(hA23, qa.z, ka.z, aw.z); STEP(hA23, qa.w, ka.w, aw.w);
                STEP(hB01, qa.x, kb.x, aw.x); STEP(hB01, qa.y, kb.y, aw.y);
                STEP(hB23, qa.z, kb.z, aw.z); STEP(hB23, qa.w, kb.w, aw.w);
                float2 f;
                f = __half22float2(hA01); sA0 += f.x; sA0 += f.y;
                f = __half22float2(hA23); sA1 += f.x; sA1 += f.y;
                f = __half22float2(hB01); sB0 += f.x; sB0 += f.y;
                f = __half22float2(hB23); sB1 += f.x; sB1 += f.y;
            }
            acc[2 * pp]     = val0 ? (sA0 + sA1) : -CUDART_INF_F;
            acc[2 * pp + 1] = val1 ? (sB0 + sB1) : -CUDART_INF_F;
        }
    }
#undef STEP

    // ---- softmax over compacted values ----
    float mx = -CUDART_INF_F;
#pragma unroll
    for (int cc = 0; cc < NC; cc++) mx = fmaxf(mx, acc[cc]);
#pragma unroll
    for (int o = 16; o; o >>= 1) mx = fmaxf(mx, __shfl_xor_sync(FULLM, mx, o));

    float sum = 0.f;
#pragma unroll
    for (int cc = 0; cc < NC; cc++) {
        float e = __expf(acc[cc] - mx);
        acc[cc] = e;
        sum += e;
    }
#pragma unroll
    for (int o = 16; o; o >>= 1) sum += __shfl_xor_sync(FULLM, sum, o);
    float inv = (sum > 0.f) ? __fdividef(1.f, sum) : 0.f;

    // ---- scatter via smem (reuse K region after barrier), dense store ----
    __syncthreads();
    float* ws = (float*)ksb + warp * LK_;
#pragma unroll
    for (int c = 0; c < NC; c++) ws[c * 32 + lane] = 0.f;
    __syncwarp();
#pragma unroll
    for (int cc = 0; cc < NC; cc++) {
        int s = cc * 32 + lane;
        if (s < nkeep) ws[stripe[s]] = acc[cc] * inv;
    }
    __syncwarp();

    float* orow = out + ((size_t)bh * LQ_ + i) * LK_;
#pragma unroll
    for (int c = 0; c < NC; c++) orow[c * 32 + lane] = ws[c * 32 + lane];
}

extern "C" void kernel_launch(void* const* d_in, const int* in_sizes, int n_in,
                              void* d_out, int out_size)
{
    const float* q   = (const float*)d_in[0];
    const float* k   = (const float*)d_in[1];
    const float* att = (const float*)d_in[2];
    const int*   m   = (const int*)d_in[3];
    float* out       = (float*)d_out;

    // K 55296 + q 1024 + a 128 + idx16 6144 = 62,592 B
    const int smem_bytes = LK_ * KSTR + ROWS * 128 + 128
                         + ROWS * LK_ * (int)sizeof(unsigned short);
    cudaFuncSetAttribute(gatv2_kernel, cudaFuncAttributeMaxDynamicSharedMemorySize, smem_bytes);

    dim3 grid(B_ * H_ * (LQ_ / ROWS));   // 768
    gatv2_kernel<<<grid, 256, smem_bytes>>>(q, k, att, m, out);
}